// round 2
// baseline (speedup 1.0000x reference)
#include <cuda_runtime.h>
#include <math.h>

#define NTOK 16384
#define DDIM 2048
#define NE   64
#define TM   64
#define KT   64
#define NTHREADS 256
#define NTILES (DDIM / KT)
#define NGRP 8
#define TOPK 8
#define TOPG 4

__device__ __forceinline__ unsigned long long pack2(float a, float b) {
    unsigned long long r;
    asm("mov.b64 %0, {%1,%2};" : "=l"(r) : "f"(a), "f"(b));
    return r;
}
__device__ __forceinline__ void unpack2(unsigned long long v, float& a, float& b) {
    asm("mov.b64 {%0,%1}, %2;" : "=f"(a), "=f"(b) : "l"(v));
}
__device__ __forceinline__ unsigned long long ffma2(unsigned long long a,
                                                    unsigned long long b,
                                                    unsigned long long c) {
    unsigned long long d;
    asm("fma.rn.f32x2 %0, %1, %2, %3;" : "=l"(d) : "l"(a), "l"(b), "l"(c));
    return d;
}

__global__ void __launch_bounds__(NTHREADS, 2) gate_kernel(
    const float* __restrict__ x,     // [NTOK, DDIM]
    const float* __restrict__ W,     // [NE, DDIM]
    const float* __restrict__ bvec,  // [NE]
    const float* __restrict__ bias,  // [1, NE]
    float* __restrict__ out)         // [NTOK*8 weights | NTOK*8 idx-as-float]
{
    extern __shared__ float s[];   // 16384 floats: buf0 xs/ws, buf1 xs/ws

    const int tid  = threadIdx.x;
    const int tz   = tid >> 7;     // K-split half
    const int tid7 = tid & 127;
    const int tx   = tid7 & 15;    // experts 4*tx .. 4*tx+3
    const int ty   = tid7 >> 4;    // tokens  8*ty .. 8*ty+7
    const int t0   = blockIdx.x * TM;

    // ---- cooperative loader setup (all 256 threads) ----
    int lqp[4];                    // swizzled dest quad-position per chunk
    int lqc[4];                    // k-quad per chunk
    const float4* xsrc[4];
    const float4* wsrc[4];
#pragma unroll
    for (int it = 0; it < 4; it++) {
        int idx = tid + it * NTHREADS;     // 0..1023
        int row = idx >> 4;                // 0..63
        int qc  = idx & 15;                // k-quad 0..15
        lqc[it] = qc;
        lqp[it] = (((row >> 2) ^ qc) << 2) + (row & 3);
        xsrc[it] = reinterpret_cast<const float4*>(x + (size_t)(t0 + row) * DDIM + 4 * qc);
        wsrc[it] = reinterpret_cast<const float4*>(W + (size_t)row * DDIM + 4 * qc);
    }

    unsigned long long acc[4][4];
#pragma unroll
    for (int i = 0; i < 4; i++)
#pragma unroll
        for (int j = 0; j < 4; j++) acc[i][j] = 0ull;

    float4 xr[4], wr[4];
    // prefetch tile 0
#pragma unroll
    for (int it = 0; it < 4; it++) { xr[it] = xsrc[it][0]; wr[it] = wsrc[it][0]; }

    // store tile into buffer (transposed + k-quad XOR swizzle)
    auto sts_tile = [&](float* xsb, float* wsb) {
#pragma unroll
        for (int it = 0; it < 4; it++) {
            const int qc = lqc[it], qp = lqp[it];
            float4 v = xr[it];
            xsb[(4 * qc + 0) * 64 + qp] = v.x;
            xsb[(4 * qc + 1) * 64 + qp] = v.y;
            xsb[(4 * qc + 2) * 64 + qp] = v.z;
            xsb[(4 * qc + 3) * 64 + qp] = v.w;
            float4 w4 = wr[it];
            wsb[(4 * qc + 0) * 64 + qp] = w4.x;
            wsb[(4 * qc + 1) * 64 + qp] = w4.y;
            wsb[(4 * qc + 2) * 64 + qp] = w4.z;
            wsb[(4 * qc + 3) * 64 + qp] = w4.w;
        }
    };

    auto compute_tile = [&](const float* xsb, const float* wsb) {
        const int kbeg = tz * 32;
#pragma unroll 4
        for (int k = kbeg; k < kbeg + 32; k++) {
            const int swz = k >> 2;  // 0..15 within tile
            const int qa = (((2 * ty)     ^ swz) << 2);
            const int qb = (((2 * ty + 1) ^ swz) << 2);
            const int qw = ((tx ^ swz) << 2);
            ulonglong2 xA = *reinterpret_cast<const ulonglong2*>(xsb + k * 64 + qa);
            ulonglong2 xB = *reinterpret_cast<const ulonglong2*>(xsb + k * 64 + qb);
            float4 wv = *reinterpret_cast<const float4*>(wsb + k * 64 + qw);
            unsigned long long xp0 = xA.x, xp1 = xA.y, xp2 = xB.x, xp3 = xB.y;
            unsigned long long wp0 = pack2(wv.x, wv.x);
            unsigned long long wp1 = pack2(wv.y, wv.y);
            unsigned long long wp2 = pack2(wv.z, wv.z);
            unsigned long long wp3 = pack2(wv.w, wv.w);
            acc[0][0] = ffma2(xp0, wp0, acc[0][0]);
            acc[0][1] = ffma2(xp0, wp1, acc[0][1]);
            acc[0][2] = ffma2(xp0, wp2, acc[0][2]);
            acc[0][3] = ffma2(xp0, wp3, acc[0][3]);
            acc[1][0] = ffma2(xp1, wp0, acc[1][0]);
            acc[1][1] = ffma2(xp1, wp1, acc[1][1]);
            acc[1][2] = ffma2(xp1, wp2, acc[1][2]);
            acc[1][3] = ffma2(xp1, wp3, acc[1][3]);
            acc[2][0] = ffma2(xp2, wp0, acc[2][0]);
            acc[2][1] = ffma2(xp2, wp1, acc[2][1]);
            acc[2][2] = ffma2(xp2, wp2, acc[2][2]);
            acc[2][3] = ffma2(xp2, wp3, acc[2][3]);
            acc[3][0] = ffma2(xp3, wp0, acc[3][0]);
            acc[3][1] = ffma2(xp3, wp1, acc[3][1]);
            acc[3][2] = ffma2(xp3, wp2, acc[3][2]);
            acc[3][3] = ffma2(xp3, wp3, acc[3][3]);
        }
    };

    sts_tile(s, s + 4096);
    __syncthreads();

#pragma unroll 1
    for (int t = 0; t < NTILES; t++) {
        const int cur = t & 1;
        if (t + 1 < NTILES) {
#pragma unroll
            for (int it = 0; it < 4; it++) {
                xsrc[it] += 16; wsrc[it] += 16;           // advance KT floats
                xr[it] = xsrc[it][0];
                wr[it] = wsrc[it][0];
            }
        }
        compute_tile(s + cur * 8192, s + cur * 8192 + 4096);
        if (t + 1 < NTILES) {
            sts_tile(s + (1 - cur) * 8192, s + (1 - cur) * 8192 + 4096);
        }
        __syncthreads();
    }

    // ---- split-K reduction: half tz=1 dumps partials, tz=0 combines ----
    unsigned long long* pbuf = reinterpret_cast<unsigned long long*>(s);
    if (tz == 1) {
#pragma unroll
        for (int i = 0; i < 4; i++)
#pragma unroll
            for (int j = 0; j < 4; j++)
                pbuf[tid7 * 16 + i * 4 + j] = acc[i][j];
    }
    __syncthreads();

    float* sc = s + 4096;   // [TM][65] score matrix (sigmoid, no bias)
    if (tz == 0) {
        float bb[4];
#pragma unroll
        for (int j = 0; j < 4; j++) bb[j] = bvec[4 * tx + j];
#pragma unroll
        for (int i = 0; i < 4; i++) {
#pragma unroll
            for (int j = 0; j < 4; j++) {
                float lo, hi, plo, phi;
                unpack2(acc[i][j], lo, hi);
                unpack2(pbuf[tid7 * 16 + i * 4 + j], plo, phi);
                lo += plo; hi += phi;
                const int e = 4 * tx + j;
                const int tA = 8 * ty + 2 * i;
                sc[(tA + 0) * 65 + e] = 1.0f / (1.0f + expf(-(lo + bb[j])));
                sc[(tA + 1) * 65 + e] = 1.0f / (1.0f + expf(-(hi + bb[j])));
            }
        }
    }
    __syncthreads();

    // ---- routing: one thread per token, exact reference semantics ----
    if (tid < TM) {
        const int t = tid;
        const int gt = t0 + t;
        const float* row = sc + t * 65;

        float sv[NE];
#pragma unroll
        for (int e = 0; e < NE; e++) sv[e] = row[e] + bias[e];

        float gs[NGRP];
#pragma unroll
        for (int g = 0; g < NGRP; g++) {
            float m1 = -1e30f, m2 = -1e30f;
#pragma unroll
            for (int j = 0; j < 8; j++) {
                float v = sv[8 * g + j];
                if (v > m1) { m2 = m1; m1 = v; }
                else if (v > m2) { m2 = v; }
            }
            gs[g] = m1 + m2;
        }

        int gmask = 0;
        for (int r = 0; r < TOPG; r++) {
            float bv = -1e30f; int bg = 0;
#pragma unroll
            for (int g = 0; g < NGRP; g++) {
                bool avail = !((gmask >> g) & 1);
                if (avail && gs[g] > bv) { bv = gs[g]; bg = g; }
            }
            gmask |= (1 << bg);
        }

        unsigned long long used = 0ull;
        for (int r = 0; r < TOPK; r++) {
            float bv = -1e30f; int be = 0;
#pragma unroll
            for (int e = 0; e < NE; e++) {
                bool ok = ((gmask >> (e >> 3)) & 1) && !((used >> e) & 1ull);
                if (ok && sv[e] > bv) { bv = sv[e]; be = e; }
            }
            used |= (1ull << be);
            out[(size_t)gt * TOPK + r] = row[be];
            out[(size_t)NTOK * TOPK + (size_t)gt * TOPK + r] = (float)be;
        }
    }
}

extern "C" void kernel_launch(void* const* d_in, const int* in_sizes, int n_in,
                              void* d_out, int out_size) {
    const float* x    = (const float*)d_in[0];
    const float* W    = (const float*)d_in[1];
    const float* b    = (const float*)d_in[2];
    const float* bias = (const float*)d_in[3];
    float* out = (float*)d_out;
    cudaFuncSetAttribute(gate_kernel, cudaFuncAttributeMaxDynamicSharedMemorySize, 65536);
    gate_kernel<<<NTOK / TM, NTHREADS, 65536>>>(x, W, b, bias, out);
}